// round 7
// baseline (speedup 1.0000x reference)
#include <cuda_runtime.h>
#include <cstdint>

// SparseLayer: 100000 independent tiny linear MLPs (5 -> 2 -> 2 -> 1), batch 128.
// Linear chain collapses per-net to v = w2 @ w1 @ w0 (1x5); out[b] = v . x[:,b].
//
// L2 strategy (126 MB L2, graph-replay steady state):
//   x   (256 MB, stream-once)      -> L2::evict_first  (don't thrash L2)
//   out (51.2 MB, write-only)      -> L2::evict_last   (stay resident; no DRAM writeback)
//   w*  (6.4 MB, reread per replay)-> L2::evict_last   (L2-resident across replays)
// Steady-state DRAM traffic ~= x reads only (256 MB).

#define N_NETS    100000
#define INTERFACE 5
#define BATCH     128

__global__ __launch_bounds__(256) void sparse_layer_kernel(
    const float* __restrict__ x,    // [N_NETS*5, 128]
    const float* __restrict__ w0,   // [N_NETS, 2, 5]
    const float* __restrict__ w1,   // [N_NETS, 2, 2]
    const float* __restrict__ w2,   // [N_NETS, 1, 2]
    float* __restrict__ out)        // [N_NETS, 128]
{
    const int warp = (blockIdx.x * blockDim.x + threadIdx.x) >> 5;
    const int lane = threadIdx.x & 31;
    if (warp >= N_NETS) return;

    uint64_t pol_first, pol_last;
    asm("createpolicy.fractional.L2::evict_first.b64 %0, 1.0;" : "=l"(pol_first));
    asm("createpolicy.fractional.L2::evict_last.b64  %0, 1.0;" : "=l"(pol_last));

    // Per-net weights (same address across the warp -> broadcast), evict_last.
    const float* W0 = w0 + (size_t)warp * 10;  // [2,5] row-major
    const float* W1 = w1 + (size_t)warp * 4;   // [2,2] row-major
    const float* W2 = w2 + (size_t)warp * 2;   // [1,2]

    float w1v[4], w2v[2], w0v[10];
#pragma unroll
    for (int i = 0; i < 4; ++i)
        asm volatile("ld.global.nc.L2::cache_hint.f32 %0, [%1], %2;"
                     : "=f"(w1v[i]) : "l"(W1 + i), "l"(pol_last));
#pragma unroll
    for (int i = 0; i < 2; ++i)
        asm volatile("ld.global.nc.L2::cache_hint.f32 %0, [%1], %2;"
                     : "=f"(w2v[i]) : "l"(W2 + i), "l"(pol_last));
#pragma unroll
    for (int i = 0; i < 10; ++i)
        asm volatile("ld.global.nc.L2::cache_hint.f32 %0, [%1], %2;"
                     : "=f"(w0v[i]) : "l"(W0 + i), "l"(pol_last));

    // u = w2 @ w1 (1x2)
    const float a0 = fmaf(w2v[1], w1v[2], w2v[0] * w1v[0]);
    const float a1 = fmaf(w2v[1], w1v[3], w2v[0] * w1v[1]);

    // v = u @ w0 (1x5)
    float v[INTERFACE];
#pragma unroll
    for (int i = 0; i < INTERFACE; ++i)
        v[i] = fmaf(a1, w0v[INTERFACE + i], a0 * w0v[i]);

    // Stream this net's x rows; each lane covers 4 contiguous batch columns.
    const float* xbase = x + (size_t)warp * INTERFACE * BATCH + lane * 4;

    float acc0 = 0.f, acc1 = 0.f, acc2 = 0.f, acc3 = 0.f;
#pragma unroll
    for (int i = 0; i < INTERFACE; ++i) {
        float r0, r1, r2, r3;
        const float* p = xbase + i * BATCH;
        asm volatile(
            "ld.global.nc.L2::cache_hint.v4.f32 {%0,%1,%2,%3}, [%4], %5;"
            : "=f"(r0), "=f"(r1), "=f"(r2), "=f"(r3)
            : "l"(p), "l"(pol_first));
        acc0 = fmaf(v[i], r0, acc0);
        acc1 = fmaf(v[i], r1, acc1);
        acc2 = fmaf(v[i], r2, acc2);
        acc3 = fmaf(v[i], r3, acc3);
    }

    // Output store: evict_last so out lines stay L2-resident across replays.
    float* op = out + (size_t)warp * BATCH + lane * 4;
    asm volatile(
        "st.global.L2::cache_hint.v4.f32 [%0], {%1,%2,%3,%4}, %5;"
        :: "l"(op), "f"(acc0), "f"(acc1), "f"(acc2), "f"(acc3), "l"(pol_last)
        : "memory");
}

extern "C" void kernel_launch(void* const* d_in, const int* in_sizes, int n_in,
                              void* d_out, int out_size)
{
    const float* x  = (const float*)d_in[0];
    const float* w0 = (const float*)d_in[1];
    const float* w1 = (const float*)d_in[2];
    const float* w2 = (const float*)d_in[3];
    float* out = (float*)d_out;

    const int warps_per_block = 256 / 32;  // 8 nets per block
    const int grid = (N_NETS + warps_per_block - 1) / warps_per_block;
    sparse_layer_kernel<<<grid, 256>>>(x, w0, w1, w2, out);
}

// round 8
// speedup vs baseline: 1.0214x; 1.0214x over previous
#include <cuda_runtime.h>
#include <cstdint>

// SparseLayer: 100000 independent tiny linear MLPs (5 -> 2 -> 2 -> 1), batch 128.
// Linear chain collapses per-net to v = w2 @ w1 @ w0 (1x5); out[b] = v . x[:,b].
//
// HBM-bound: ~256 MB of stream-once x dominates. x loads carry L2::evict_first
// (keeps L2 free to absorb out writebacks + weight rereads — R4's 8.5% win).
// This round: front-batch the five 16B x loads (MLP from instr 0) and let the
// compiler schedule vectorized weight loads into their latency shadow.

#define N_NETS    100000
#define INTERFACE 5
#define BATCH     128

__global__ __launch_bounds__(256) void sparse_layer_kernel(
    const float* __restrict__ x,    // [N_NETS*5, 128]
    const float* __restrict__ w0,   // [N_NETS, 2, 5]
    const float* __restrict__ w1,   // [N_NETS, 2, 2]
    const float* __restrict__ w2,   // [N_NETS, 1, 2]
    float* __restrict__ out)        // [N_NETS, 128]
{
    const int warp = (blockIdx.x * blockDim.x + threadIdx.x) >> 5;
    const int lane = threadIdx.x & 31;
    if (warp >= N_NETS) return;

    uint64_t pol_first;
    asm("createpolicy.fractional.L2::evict_first.b64 %0, 1.0;" : "=l"(pol_first));

    // ---- Front-batch the 5 bandwidth-carrying x loads (evict_first) ----
    const float* xbase = x + (size_t)warp * INTERFACE * BATCH + lane * 4;
    float r[INTERFACE][4];
#pragma unroll
    for (int i = 0; i < INTERFACE; ++i) {
        const float* p = xbase + i * BATCH;
        asm volatile(
            "ld.global.nc.L2::cache_hint.v4.f32 {%0,%1,%2,%3}, [%4], %5;"
            : "=f"(r[i][0]), "=f"(r[i][1]), "=f"(r[i][2]), "=f"(r[i][3])
            : "l"(p), "l"(pol_first));
    }

    // ---- Weight loads: plain __ldg, vectorized per alignment; compiler is
    // free to schedule these into the x-load latency shadow ----
    // w1: net*4 floats = 16B aligned -> float4
    const float4 w1v = __ldg(reinterpret_cast<const float4*>(w1) + warp);
    // w2: net*2 floats = 8B aligned -> float2
    const float2 w2v = __ldg(reinterpret_cast<const float2*>(w2) + warp);
    // w0: net*10 floats = 8B aligned -> 5x float2
    const float2* W0p = reinterpret_cast<const float2*>(w0 + (size_t)warp * 10);
    float2 w0v[5];
#pragma unroll
    for (int i = 0; i < 5; ++i) w0v[i] = __ldg(W0p + i);
    const float* W0 = &w0v[0].x;   // 10 contiguous floats in registers

    // u = w2 @ w1 (1x2):  u[h] = w2[0]*w1[0][h] + w2[1]*w1[1][h]
    const float a0 = fmaf(w2v.y, w1v.z, w2v.x * w1v.x);
    const float a1 = fmaf(w2v.y, w1v.w, w2v.x * w1v.y);

    // v = u @ w0 (1x5)
    float v[INTERFACE];
#pragma unroll
    for (int i = 0; i < INTERFACE; ++i)
        v[i] = fmaf(a1, W0[INTERFACE + i], a0 * W0[i]);

    // ---- Accumulate ----
    float acc0 = 0.f, acc1 = 0.f, acc2 = 0.f, acc3 = 0.f;
#pragma unroll
    for (int i = 0; i < INTERFACE; ++i) {
        acc0 = fmaf(v[i], r[i][0], acc0);
        acc1 = fmaf(v[i], r[i][1], acc1);
        acc2 = fmaf(v[i], r[i][2], acc2);
        acc3 = fmaf(v[i], r[i][3], acc3);
    }

    reinterpret_cast<float4*>(out)[(size_t)warp * (BATCH / 4) + lane] =
        make_float4(acc0, acc1, acc2, acc3);
}

extern "C" void kernel_launch(void* const* d_in, const int* in_sizes, int n_in,
                              void* d_out, int out_size)
{
    const float* x  = (const float*)d_in[0];
    const float* w0 = (const float*)d_in[1];
    const float* w1 = (const float*)d_in[2];
    const float* w2 = (const float*)d_in[3];
    float* out = (float*)d_out;

    const int warps_per_block = 256 / 32;  // 8 nets per block
    const int grid = (N_NETS + warps_per_block - 1) / warps_per_block;
    sparse_layer_kernel<<<grid, 256>>>(x, w0, w1, w2, out);
}